// round 1
// baseline (speedup 1.0000x reference)
#include <cuda_runtime.h>
#include <cuda_bf16.h>

// Problem shape: B=32, F=32, N=36, D=2048, P=512
#define MTOT  36864      // B*F*N rows
#define NOBJ  36
#define DDIM  2048
#define PDIM  512
#define NBF   1024       // B*F

// Scratch (allocation-free rule: __device__ globals)
__device__ float g_sig[(size_t)MTOT * PDIM];
__device__ float g_psi[(size_t)MTOT * PDIM];
__device__ float g_v  [(size_t)MTOT * PDIM];

// ---------------------------------------------------------------------------
// Fused projection GEMM: for z in {proj, sigma, psi, r}:
//   C_z[36864, 512] = X[36864, 2048] @ W_z[2048, 512] (+ b_z)
// 128x128 block tile, BK=8, 256 threads, 8x8 per-thread micro-tile.
// gridDim.z = 4 so concurrent z-blocks hit the same X tiles in L2.
// ---------------------------------------------------------------------------
__global__ void __launch_bounds__(256, 2) proj_gemm_kernel(
    const float* __restrict__ X,
    const float* __restrict__ Wp, const float* __restrict__ bp,
    const float* __restrict__ Ws, const float* __restrict__ bs,
    const float* __restrict__ Wq, const float* __restrict__ bq,
    const float* __restrict__ Wr,
    float* __restrict__ rfeat_out)
{
    const float* W;
    const float* bias;
    float* C;
    switch (blockIdx.z) {
        case 0:  W = Wp; bias = bp;      C = rfeat_out; break;
        case 1:  W = Ws; bias = bs;      C = g_sig;     break;
        case 2:  W = Wq; bias = bq;      C = g_psi;     break;
        default: W = Wr; bias = nullptr; C = g_v;       break;
    }

    __shared__ float As[8][132];   // padded stride to dodge store conflicts
    __shared__ float Bs[8][128];

    const int tid  = threadIdx.x;
    const int brow = blockIdx.y * 128;
    const int bcol = blockIdx.x * 128;

    // A tile load: 128 rows x 8 cols, one float4 per thread
    const int arow = tid >> 1;            // 0..127
    const int acol = (tid & 1) * 4;       // 0 or 4
    // B tile load: 8 rows x 128 cols, one float4 per thread
    const int bkrow = tid >> 5;           // 0..7
    const int bncol = (tid & 31) * 4;     // 0..124
    // per-thread output micro-tile origin
    const int mr = (tid >> 4) * 8;        // 0..120
    const int nc = (tid & 15) * 8;        // 0..120

    const float* Aptr = X + (size_t)(brow + arow) * DDIM + acol;
    const float* Bptr = W + (size_t)bkrow * PDIM + bcol + bncol;

    float acc[8][8];
    #pragma unroll
    for (int i = 0; i < 8; i++)
        #pragma unroll
        for (int j = 0; j < 8; j++) acc[i][j] = 0.0f;

    for (int kt = 0; kt < DDIM; kt += 8) {
        float4 av = *(const float4*)(Aptr + kt);
        float4 bv = *(const float4*)(Bptr + (size_t)kt * PDIM);

        As[acol + 0][arow] = av.x;
        As[acol + 1][arow] = av.y;
        As[acol + 2][arow] = av.z;
        As[acol + 3][arow] = av.w;
        *(float4*)&Bs[bkrow][bncol] = bv;
        __syncthreads();

        #pragma unroll
        for (int k = 0; k < 8; ++k) {
            float ar[8], br[8];
            *(float4*)&ar[0] = *(const float4*)&As[k][mr];
            *(float4*)&ar[4] = *(const float4*)&As[k][mr + 4];
            *(float4*)&br[0] = *(const float4*)&Bs[k][nc];
            *(float4*)&br[4] = *(const float4*)&Bs[k][nc + 4];
            #pragma unroll
            for (int i = 0; i < 8; i++)
                #pragma unroll
                for (int j = 0; j < 8; j++)
                    acc[i][j] = fmaf(ar[i], br[j], acc[i][j]);
        }
        __syncthreads();
    }

    float bb[8];
    #pragma unroll
    for (int j = 0; j < 8; j++)
        bb[j] = bias ? bias[bcol + nc + j] : 0.0f;

    #pragma unroll
    for (int i = 0; i < 8; i++) {
        float* Cp = C + (size_t)(brow + mr + i) * PDIM + bcol + nc;
        float4 o0, o1;
        o0.x = acc[i][0] + bb[0]; o0.y = acc[i][1] + bb[1];
        o0.z = acc[i][2] + bb[2]; o0.w = acc[i][3] + bb[3];
        o1.x = acc[i][4] + bb[4]; o1.y = acc[i][5] + bb[5];
        o1.z = acc[i][6] + bb[6]; o1.w = acc[i][7] + bb[7];
        *(float4*)(Cp)     = o0;
        *(float4*)(Cp + 4) = o1;
    }
}

// ---------------------------------------------------------------------------
// Per-(b,f) attention: scores = sig @ psi^T  [36x36], softmax rows,
// r_hat = A @ v  [36x512]. One CTA per (b,f); sig/psi/v staged in smem.
// ---------------------------------------------------------------------------
#define RS 513                      // padded row stride (conflict-free scalar LDS)
#define SC 37                       // padded score row stride
#define ATTN_SMEM_FLOATS (2 * NOBJ * RS + NOBJ * SC)

__global__ void __launch_bounds__(256) attn_kernel(float* __restrict__ out)
{
    extern __shared__ float sm[];
    float* s_psi = sm;                    // [NOBJ][RS]
    float* s_buf = sm + NOBJ * RS;        // [NOBJ][RS]  sig, later v
    float* s_sc  = sm + 2 * NOBJ * RS;    // [NOBJ][SC]

    const int bf  = blockIdx.x;
    const int tid = threadIdx.x;

    const float* sigg = g_sig + (size_t)bf * NOBJ * PDIM;
    const float* psig = g_psi + (size_t)bf * NOBJ * PDIM;
    const float* vg   = g_v   + (size_t)bf * NOBJ * PDIM;

    // Stage sig -> s_buf, psi -> s_psi
    for (int i = tid; i < NOBJ * PDIM; i += 256) {
        int n = i >> 9, p = i & 511;
        s_buf[n * RS + p] = sigg[i];
        s_psi[n * RS + p] = psig[i];
    }
    __syncthreads();

    // Scores: 16x16 thread grid, each covers a 3x3 set of (n, m) pairs
    {
        const int ti = tid & 15;       // m group
        const int tj = tid >> 4;       // n group
        float acc[3][3];
        #pragma unroll
        for (int a = 0; a < 3; a++)
            #pragma unroll
            for (int b = 0; b < 3; b++) acc[a][b] = 0.0f;

        const bool nok2 = (tj + 32) < NOBJ;
        const bool mok2 = (ti + 32) < NOBJ;

        for (int k = 0; k < PDIM; k++) {
            float a0 = s_buf[(tj)      * RS + k];
            float a1 = s_buf[(tj + 16) * RS + k];
            float a2 = nok2 ? s_buf[(tj + 32) * RS + k] : 0.0f;
            float b0 = s_psi[(ti)      * RS + k];
            float b1 = s_psi[(ti + 16) * RS + k];
            float b2 = mok2 ? s_psi[(ti + 32) * RS + k] : 0.0f;
            acc[0][0] = fmaf(a0, b0, acc[0][0]);
            acc[0][1] = fmaf(a0, b1, acc[0][1]);
            acc[0][2] = fmaf(a0, b2, acc[0][2]);
            acc[1][0] = fmaf(a1, b0, acc[1][0]);
            acc[1][1] = fmaf(a1, b1, acc[1][1]);
            acc[1][2] = fmaf(a1, b2, acc[1][2]);
            acc[2][0] = fmaf(a2, b0, acc[2][0]);
            acc[2][1] = fmaf(a2, b1, acc[2][1]);
            acc[2][2] = fmaf(a2, b2, acc[2][2]);
        }
        #pragma unroll
        for (int a = 0; a < 3; a++) {
            int n = tj + 16 * a;
            if (n >= NOBJ) break;
            #pragma unroll
            for (int b = 0; b < 3; b++) {
                int m = ti + 16 * b;
                if (m < NOBJ) s_sc[n * SC + m] = acc[a][b];
            }
        }
    }
    __syncthreads();

    // Row softmax (one thread per row)
    if (tid < NOBJ) {
        float mx = -1e30f;
        #pragma unroll
        for (int m = 0; m < NOBJ; m++) mx = fmaxf(mx, s_sc[tid * SC + m]);
        float s = 0.0f;
        #pragma unroll
        for (int m = 0; m < NOBJ; m++) {
            float e = __expf(s_sc[tid * SC + m] - mx);
            s_sc[tid * SC + m] = e;
            s += e;
        }
        float inv = 1.0f / s;
        #pragma unroll
        for (int m = 0; m < NOBJ; m++) s_sc[tid * SC + m] *= inv;
    }
    __syncthreads();

    // Overwrite s_buf with v
    for (int i = tid; i < NOBJ * PDIM; i += 256) {
        int n = i >> 9, p = i & 511;
        s_buf[n * RS + p] = vg[i];
    }
    __syncthreads();

    // r_hat = A @ v. Each thread owns columns p = tid, tid+256.
    float* rhat = out + (size_t)MTOT * PDIM + (size_t)bf * NOBJ * PDIM;
    #pragma unroll
    for (int p0 = 0; p0 < PDIM; p0 += 256) {
        int p = p0 + tid;
        float vr[NOBJ];
        #pragma unroll
        for (int m = 0; m < NOBJ; m++) vr[m] = s_buf[m * RS + p];
        #pragma unroll 4
        for (int n = 0; n < NOBJ; n++) {
            float s = 0.0f;
            #pragma unroll
            for (int m = 0; m < NOBJ; m++)
                s = fmaf(s_sc[n * SC + m], vr[m], s);
            rhat[n * PDIM + p] = s;
        }
    }
}

// ---------------------------------------------------------------------------
extern "C" void kernel_launch(void* const* d_in, const int* in_sizes, int n_in,
                              void* d_out, int out_size)
{
    const float* X   = (const float*)d_in[0];   // [B,F,N,D]
    const float* Wp  = (const float*)d_in[1];   // [D,P]
    const float* bp  = (const float*)d_in[2];   // [P]
    const float* Ws  = (const float*)d_in[3];
    const float* bs  = (const float*)d_in[4];
    const float* Wq  = (const float*)d_in[5];
    const float* bq  = (const float*)d_in[6];
    const float* Wr  = (const float*)d_in[7];
    float* out = (float*)d_out;                 // [r_feat | r_hat], each MTOT*PDIM

    // GEMM: grid (N/128, M/128, 4 projections)
    dim3 ggrid(PDIM / 128, MTOT / 128, 4);
    proj_gemm_kernel<<<ggrid, 256>>>(X, Wp, bp, Ws, bs, Wq, bq, Wr, out);

    // Attention: one CTA per (b,f)
    static const int smem_bytes = ATTN_SMEM_FLOATS * (int)sizeof(float);
    cudaFuncSetAttribute(attn_kernel,
                         cudaFuncAttributeMaxDynamicSharedMemorySize, smem_bytes);
    attn_kernel<<<NBF, 256, smem_bytes>>>(out);
}

// round 3
// speedup vs baseline: 2.3231x; 2.3231x over previous
#include <cuda_runtime.h>
#include <cuda_bf16.h>
#include <cstdint>

// Problem shape: B=32, F=32, N=36, D=2048, P=512
#define MTOT  36864
#define NOBJ  36
#define DDIM  2048
#define PDIM  512
#define NBF   1024

// ---------------------------------------------------------------------------
// Scratch (allocation-free rule: __device__ globals)
// ---------------------------------------------------------------------------
__device__ float g_sig[(size_t)MTOT * PDIM];
__device__ float g_psi[(size_t)MTOT * PDIM];
__device__ float g_v  [(size_t)MTOT * PDIM];
// W transposed + bf16-split: layout [proj][P][D]
__device__ __nv_bfloat16 g_wt_hi[(size_t)4 * PDIM * DDIM];
__device__ __nv_bfloat16 g_wt_lo[(size_t)4 * PDIM * DDIM];

// ---------------------------------------------------------------------------
// PTX helpers (plain sm_80-era instructions only — no 'a'-features)
// ---------------------------------------------------------------------------
__device__ __forceinline__ uint32_t smem_u32(const void* p) {
    uint32_t a;
    asm("{ .reg .u64 t; cvta.to.shared.u64 t, %1; cvt.u32.u64 %0, t; }" : "=r"(a) : "l"(p));
    return a;
}
__device__ __forceinline__ void cp16(uint32_t saddr, const void* g) {
    asm volatile("cp.async.ca.shared.global [%0], [%1], 16;" :: "r"(saddr), "l"(g));
}
__device__ __forceinline__ void cp_commit() {
    asm volatile("cp.async.commit_group;" ::: "memory");
}
__device__ __forceinline__ void cp_wait0() {
    asm volatile("cp.async.wait_group 0;" ::: "memory");
}
__device__ __forceinline__ void ldsm_x4(uint32_t* r, uint32_t addr) {
    asm volatile("ldmatrix.sync.aligned.m8n8.x4.shared.b16 {%0,%1,%2,%3}, [%4];"
                 : "=r"(r[0]), "=r"(r[1]), "=r"(r[2]), "=r"(r[3]) : "r"(addr));
}
__device__ __forceinline__ void mma_bf16(float* d, const uint32_t* a,
                                         uint32_t b0, uint32_t b1) {
    asm volatile(
        "mma.sync.aligned.m16n8k16.row.col.f32.bf16.bf16.f32 "
        "{%0,%1,%2,%3}, {%4,%5,%6,%7}, {%8,%9}, {%0,%1,%2,%3};"
        : "+f"(d[0]), "+f"(d[1]), "+f"(d[2]), "+f"(d[3])
        : "r"(a[0]), "r"(a[1]), "r"(a[2]), "r"(a[3]), "r"(b0), "r"(b1));
}
__device__ __forceinline__ uint32_t pack_bf2(__nv_bfloat16 a, __nv_bfloat16 b) {
    __nv_bfloat162 t;
    t.x = a; t.y = b;
    return *reinterpret_cast<uint32_t*>(&t);
}
__device__ __forceinline__ void cvt8(const float4 f0, const float4 f1, uint4& hu, uint4& lu) {
    float f[8] = {f0.x, f0.y, f0.z, f0.w, f1.x, f1.y, f1.z, f1.w};
    __nv_bfloat16 h[8], l[8];
    #pragma unroll
    for (int i = 0; i < 8; i++) {
        h[i] = __float2bfloat16_rn(f[i]);
        l[i] = __float2bfloat16_rn(f[i] - __bfloat162float(h[i]));
    }
    hu.x = pack_bf2(h[0], h[1]); hu.y = pack_bf2(h[2], h[3]);
    hu.z = pack_bf2(h[4], h[5]); hu.w = pack_bf2(h[6], h[7]);
    lu.x = pack_bf2(l[0], l[1]); lu.y = pack_bf2(l[2], l[3]);
    lu.z = pack_bf2(l[4], l[5]); lu.w = pack_bf2(l[6], l[7]);
}

// ---------------------------------------------------------------------------
// Prep: transpose + bf16-split W[D,P] -> Wt_{hi,lo}[proj][P][D]
// ---------------------------------------------------------------------------
__global__ void prep_kernel(const float* __restrict__ Wp, const float* __restrict__ Ws,
                            const float* __restrict__ Wq, const float* __restrict__ Wr)
{
    __shared__ float t[32][33];
    const float* W;
    switch (blockIdx.z) {
        case 0:  W = Wp; break;
        case 1:  W = Ws; break;
        case 2:  W = Wq; break;
        default: W = Wr; break;
    }
    const int p0 = blockIdx.x * 32, d0 = blockIdx.y * 32;
    const int tx = threadIdx.x, ty = threadIdx.y;
    #pragma unroll
    for (int k = 0; k < 4; k++)
        t[ty + k * 8][tx] = W[(size_t)(d0 + ty + k * 8) * PDIM + p0 + tx];
    __syncthreads();
    #pragma unroll
    for (int k = 0; k < 4; k++) {
        const int p = p0 + ty + k * 8;
        const float v = t[tx][ty + k * 8];
        __nv_bfloat16 h = __float2bfloat16_rn(v);
        __nv_bfloat16 l = __float2bfloat16_rn(v - __bfloat162float(h));
        const size_t o = ((size_t)blockIdx.z * PDIM + p) * DDIM + d0 + tx;
        g_wt_hi[o] = h;
        g_wt_lo[o] = l;
    }
}

// ---------------------------------------------------------------------------
// bf16x3 GEMM via mma.sync: CTA tile 128x128, BK=32, 8 warps (4M x 2N),
// warp tile 32x64. Double-buffered smem; cp.async for pre-split W tiles;
// X converted fp32 -> bf16 hi/lo in registers.
// ---------------------------------------------------------------------------
#define BK      32
#define PAD     40            // smem row stride in bf16 (conflict-free ldmatrix)
#define OFF_AH  0
#define OFF_AL  10240
#define OFF_BH  20480
#define OFF_BL  30720
#define STAGE   40960
#define NCHUNK  (DDIM / BK)   // 64
#define GEMM_SMEM (2 * STAGE)

__global__ void __launch_bounds__(256, 1) gemm_kernel(
    const float* __restrict__ X,
    const float* __restrict__ bp, const float* __restrict__ bs,
    const float* __restrict__ bq,
    float* __restrict__ out)
{
    extern __shared__ char smem[];
    __shared__ float s_bias[128];
    const uint32_t sb = smem_u32(smem);

    const int tid  = threadIdx.x;
    const int proj = blockIdx.x >> 2;
    const int bcol = (blockIdx.x & 3) * 128;
    const int brow = blockIdx.y * 128;

    float* C;
    const float* bias;
    switch (proj) {
        case 0:  C = out;   bias = bp;      break;
        case 1:  C = g_sig; bias = bs;      break;
        case 2:  C = g_psi; bias = bq;      break;
        default: C = g_v;   bias = nullptr; break;
    }
    if (tid < 128) s_bias[tid] = bias ? bias[bcol + tid] : 0.0f;

    const int lane = tid & 31, wid = tid >> 5;
    const int warp_m = (wid & 3) * 32;
    const int warp_n = (wid >> 2) * 64;

    // gmem staging assignments
    const int arow = tid >> 1;             // 0..127
    const int acb  = (tid & 1) * 16;       // bf16 col base 0/16
    const float* aptr = X + (size_t)(brow + arow) * DDIM + acb;

    const int bro = tid >> 1;              // B row (n) 0..127
    const int bcb = (tid & 1) * 16;        // bf16 col base 0/16
    const __nv_bfloat16* wtH = g_wt_hi + (size_t)(proj * PDIM + bcol + bro) * DDIM + bcb;
    const __nv_bfloat16* wtL = g_wt_lo + (size_t)(proj * PDIM + bcol + bro) * DDIM + bcb;

    // ldmatrix per-lane address pieces
    const int a_r   = warp_m + (lane & 15);          // A row
    const int a_cs  = (lane >> 4) * 8;               // A col select (k half of 8)
    const int b_r   = warp_n + (lane >> 4) * 8 + (lane & 7);  // B row (n)
    const int b_cs  = ((lane >> 3) & 1) * 8;         // B col select

    float acc[2][8][4];
    #pragma unroll
    for (int mt = 0; mt < 2; mt++)
        #pragma unroll
        for (int n = 0; n < 8; n++)
            #pragma unroll
            for (int q = 0; q < 4; q++) acc[mt][n][q] = 0.0f;

    // ---- gmem load helpers (macros inline) ----
    float4 fA[4];
    #define LOAD_A_REGS(ch) do { \
        const float* p_ = aptr + (ch) * BK; \
        fA[0] = *(const float4*)(p_ + 0); \
        fA[1] = *(const float4*)(p_ + 4); \
        fA[2] = *(const float4*)(p_ + 8); \
        fA[3] = *(const float4*)(p_ + 12); \
    } while (0)

    #define STORE_A_SMEM(st_) do { \
        uint4 h0, l0, h1, l1; \
        cvt8(fA[0], fA[1], h0, l0); \
        cvt8(fA[2], fA[3], h1, l1); \
        const uint32_t o_ = (st_) + (uint32_t)(arow * PAD + acb) * 2; \
        *(uint4*)(smem + o_ + OFF_AH)      = h0; \
        *(uint4*)(smem + o_ + OFF_AH + 16) = h1; \
        *(uint4*)(smem + o_ + OFF_AL)      = l0; \
        *(uint4*)(smem + o_ + OFF_AL + 16) = l1; \
    } while (0)

    #define ISSUE_B_CP(ch, st_) do { \
        const uint32_t o_ = sb + (st_) + (uint32_t)(bro * PAD + bcb) * 2; \
        cp16(o_ + OFF_BH,      wtH + (ch) * BK); \
        cp16(o_ + OFF_BH + 16, wtH + (ch) * BK + 8); \
        cp16(o_ + OFF_BL,      wtL + (ch) * BK); \
        cp16(o_ + OFF_BL + 16, wtL + (ch) * BK + 8); \
        cp_commit(); \
    } while (0)

    // prologue: chunk 0
    ISSUE_B_CP(0, 0);
    LOAD_A_REGS(0);
    STORE_A_SMEM(0u);
    cp_wait0();
    __syncthreads();

    for (int ch = 0; ch < NCHUNK; ch++) {
        const uint32_t cur = (ch & 1) * STAGE;
        const uint32_t nxt = ((ch + 1) & 1) * STAGE;

        if (ch + 1 < NCHUNK) {
            ISSUE_B_CP(ch + 1, nxt);
            LOAD_A_REGS(ch + 1);
        }

        // compute on cur
        const uint32_t sAh = sb + cur + OFF_AH;
        const uint32_t sAl = sb + cur + OFF_AL;
        const uint32_t sBh = sb + cur + OFF_BH;
        const uint32_t sBl = sb + cur + OFF_BL;

        #pragma unroll
        for (int ks = 0; ks < 2; ks++) {
            uint32_t ah[2][4], al[2][4];
            #pragma unroll
            for (int mt = 0; mt < 2; mt++) {
                const uint32_t ao = (uint32_t)((a_r + mt * 16) * PAD + ks * 16 + a_cs) * 2;
                ldsm_x4(ah[mt], sAh + ao);
                ldsm_x4(al[mt], sAl + ao);
            }
            #pragma unroll
            for (int ng = 0; ng < 4; ng++) {
                uint32_t bh[4], bl[4];
                const uint32_t bo = (uint32_t)((b_r + ng * 16) * PAD + ks * 16 + b_cs) * 2;
                ldsm_x4(bh, sBh + bo);
                ldsm_x4(bl, sBl + bo);
                #pragma unroll
                for (int mt = 0; mt < 2; mt++) {
                    mma_bf16(acc[mt][ng * 2],     ah[mt], bh[0], bh[1]);
                    mma_bf16(acc[mt][ng * 2],     ah[mt], bl[0], bl[1]);
                    mma_bf16(acc[mt][ng * 2],     al[mt], bh[0], bh[1]);
                    mma_bf16(acc[mt][ng * 2 + 1], ah[mt], bh[2], bh[3]);
                    mma_bf16(acc[mt][ng * 2 + 1], ah[mt], bl[2], bl[3]);
                    mma_bf16(acc[mt][ng * 2 + 1], al[mt], bh[2], bh[3]);
                }
            }
        }

        if (ch + 1 < NCHUNK) {
            STORE_A_SMEM(nxt);
            cp_wait0();
            __syncthreads();
        }
    }

    // epilogue
    #pragma unroll
    for (int mt = 0; mt < 2; mt++) {
        const int r0 = brow + warp_m + mt * 16 + (lane >> 2);
        #pragma unroll
        for (int n8 = 0; n8 < 8; n8++) {
            const int c = warp_n + n8 * 8 + (lane & 3) * 2;
            float2 v0, v1;
            v0.x = acc[mt][n8][0] + s_bias[c];
            v0.y = acc[mt][n8][1] + s_bias[c + 1];
            v1.x = acc[mt][n8][2] + s_bias[c];
            v1.y = acc[mt][n8][3] + s_bias[c + 1];
            *(float2*)(C + (size_t)r0 * PDIM + bcol + c)       = v0;
            *(float2*)(C + (size_t)(r0 + 8) * PDIM + bcol + c) = v1;
        }
    }
}

// ---------------------------------------------------------------------------
// Per-(b,f) attention: scores = sig @ psi^T [36x36], softmax, r_hat = A @ v.
// ---------------------------------------------------------------------------
#define RS 516
#define SC 37
#define ATTN_SMEM_FLOATS (2 * NOBJ * RS + NOBJ * SC)

__global__ void __launch_bounds__(256) attn_kernel(float* __restrict__ out)
{
    extern __shared__ float sm[];
    float* s_psi = sm;
    float* s_buf = sm + NOBJ * RS;
    float* s_sc  = sm + 2 * NOBJ * RS;

    const int bf  = blockIdx.x;
    const int tid = threadIdx.x;

    const float* sigg = g_sig + (size_t)bf * NOBJ * PDIM;
    const float* psig = g_psi + (size_t)bf * NOBJ * PDIM;
    const float* vg   = g_v   + (size_t)bf * NOBJ * PDIM;

    for (int i = tid; i < NOBJ * 128; i += 256) {
        const int n = i >> 7, p4 = (i & 127) << 2;
        *(float4*)&s_buf[n * RS + p4] = *(const float4*)&sigg[n * PDIM + p4];
        *(float4*)&s_psi[n * RS + p4] = *(const float4*)&psig[n * PDIM + p4];
    }
    __syncthreads();

    {
        const int ti = tid & 15;
        const int tj = tid >> 4;
        const bool nok2 = (tj + 32) < NOBJ;
        const bool mok2 = (ti + 32) < NOBJ;
        const int tj2 = nok2 ? tj + 32 : 0;
        const int ti2 = mok2 ? ti + 32 : 0;

        float acc[3][3];
        #pragma unroll
        for (int a = 0; a < 3; a++)
            #pragma unroll
            for (int b = 0; b < 3; b++) acc[a][b] = 0.0f;

        for (int k = 0; k < PDIM; k += 4) {
            const float4 a0 = *(const float4*)&s_buf[(tj)      * RS + k];
            const float4 a1 = *(const float4*)&s_buf[(tj + 16) * RS + k];
            const float4 a2 = *(const float4*)&s_buf[(tj2)     * RS + k];
            const float4 b0 = *(const float4*)&s_psi[(ti)      * RS + k];
            const float4 b1 = *(const float4*)&s_psi[(ti + 16) * RS + k];
            const float4 b2 = *(const float4*)&s_psi[(ti2)     * RS + k];
            acc[0][0] += a0.x*b0.x + a0.y*b0.y + a0.z*b0.z + a0.w*b0.w;
            acc[0][1] += a0.x*b1.x + a0.y*b1.y + a0.z*b1.z + a0.w*b1.w;
            acc[0][2] += a0.x*b2.x + a0.y*b2.y + a0.z*b2.z + a0.w*b2.w;
            acc[1][0] += a1.x*b0.x + a1.y*b0.y + a1.z*b0.z + a1.w*b0.w;
            acc[1][1] += a1.x*b1.x + a1.y*b1.y + a1.z*b1.z + a1.w*b1.w;
            acc[1][2] += a1.x*b2.x + a1.y*b2.y + a1.z*b2.z + a1.w*b2.w;
            acc[2][0] += a2.x*b0.x + a2.y*b0.y + a2.z*b0.z + a2.w*b0.w;
            acc[2][1] += a2.x*b1.x + a2.y*b1.y + a2.z*b1.z + a2.w*b1.w;
            acc[2][2] += a2.x*b2.x + a2.y*b2.y + a2.z*b2.z + a2.w*b2.w;
        }
        #pragma unroll
        for (int a = 0; a < 3; a++) {
            const int n = tj + 16 * a;
            if (n >= NOBJ) break;
            #pragma unroll
            for (int b = 0; b < 3; b++) {
                const int m = ti + 16 * b;
                if (m < NOBJ) s_sc[n * SC + m] = acc[a][b];
            }
        }
    }
    __syncthreads();

    if (tid < NOBJ) {
        float mx = -1e30f;
        #pragma unroll
        for (int m = 0; m < NOBJ; m++) mx = fmaxf(mx, s_sc[tid * SC + m]);
        float s = 0.0f;
        #pragma unroll
        for (int m = 0; m < NOBJ; m++) {
            const float e = __expf(s_sc[tid * SC + m] - mx);
            s_sc[tid * SC + m] = e;
            s += e;
        }
        const float inv = 1.0f / s;
        #pragma unroll
        for (int m = 0; m < NOBJ; m++) s_sc[tid * SC + m] *= inv;
    }
    __syncthreads();

    for (int i = tid; i < NOBJ * 128; i += 256) {
        const int n = i >> 7, p4 = (i & 127) << 2;
        *(float4*)&s_buf[n * RS + p4] = *(const float4*)&vg[n * PDIM + p4];
    }
    __syncthreads();

    float* rhat = out + (size_t)MTOT * PDIM + (size_t)bf * NOBJ * PDIM;
    #pragma unroll
    for (int p0 = 0; p0 < PDIM; p0 += 256) {
        const int p = p0 + tid;
        float vr[NOBJ];
        #pragma unroll
        for (int m = 0; m < NOBJ; m++) vr[m] = s_buf[m * RS + p];
        #pragma unroll 4
        for (int n = 0; n < NOBJ; n++) {
            float s = 0.0f;
            #pragma unroll
            for (int m = 0; m < NOBJ; m++)
                s = fmaf(s_sc[n * SC + m], vr[m], s);
            rhat[n * PDIM + p] = s;
        }
    }
}

// ---------------------------------------------------------------------------
extern "C" void kernel_launch(void* const* d_in, const int* in_sizes, int n_in,
                              void* d_out, int out_size)
{
    const float* X   = (const float*)d_in[0];
    const float* Wp  = (const float*)d_in[1];
    const float* bp  = (const float*)d_in[2];
    const float* Ws  = (const float*)d_in[3];
    const float* bs  = (const float*)d_in[4];
    const float* Wq  = (const float*)d_in[5];
    const float* bq  = (const float*)d_in[6];
    const float* Wr  = (const float*)d_in[7];
    float* out = (float*)d_out;

    prep_kernel<<<dim3(PDIM / 32, DDIM / 32, 4), dim3(32, 8)>>>(Wp, Ws, Wq, Wr);

    cudaFuncSetAttribute(gemm_kernel,
                         cudaFuncAttributeMaxDynamicSharedMemorySize, GEMM_SMEM);
    gemm_kernel<<<dim3(16, MTOT / 128), 256, GEMM_SMEM>>>(X, bp, bs, bq, out);

    const int attn_smem = ATTN_SMEM_FLOATS * (int)sizeof(float);
    cudaFuncSetAttribute(attn_kernel,
                         cudaFuncAttributeMaxDynamicSharedMemorySize, attn_smem);
    attn_kernel<<<NBF, 256, attn_smem>>>(out);
}

// round 4
// speedup vs baseline: 2.6304x; 1.1323x over previous
#include <cuda_runtime.h>
#include <cuda_bf16.h>
#include <cstdint>

// Problem shape: B=32, F=32, N=36, D=2048, P=512
#define MTOT  36864
#define NOBJ  36
#define DDIM  2048
#define PDIM  512
#define NBF   1024

// ---------------------------------------------------------------------------
// Scratch (allocation-free rule: __device__ globals)
// ---------------------------------------------------------------------------
__device__ float g_sig[(size_t)MTOT * PDIM];
__device__ float g_psi[(size_t)MTOT * PDIM];
__device__ float g_v  [(size_t)MTOT * PDIM];
// W transposed + bf16-split: layout [proj][P][D]
__device__ __nv_bfloat16 g_wt_hi[(size_t)4 * PDIM * DDIM];
__device__ __nv_bfloat16 g_wt_lo[(size_t)4 * PDIM * DDIM];

// ---------------------------------------------------------------------------
// PTX helpers (plain sm_80-era instructions only — no 'a'-features)
// ---------------------------------------------------------------------------
__device__ __forceinline__ uint32_t smem_u32(const void* p) {
    uint32_t a;
    asm("{ .reg .u64 t; cvta.to.shared.u64 t, %1; cvt.u32.u64 %0, t; }" : "=r"(a) : "l"(p));
    return a;
}
__device__ __forceinline__ void cp16(uint32_t saddr, const void* g) {
    asm volatile("cp.async.ca.shared.global [%0], [%1], 16;" :: "r"(saddr), "l"(g));
}
__device__ __forceinline__ void cp_commit() {
    asm volatile("cp.async.commit_group;" ::: "memory");
}
__device__ __forceinline__ void cp_wait0() {
    asm volatile("cp.async.wait_group 0;" ::: "memory");
}
__device__ __forceinline__ void ldsm_x4(uint32_t* r, uint32_t addr) {
    asm volatile("ldmatrix.sync.aligned.m8n8.x4.shared.b16 {%0,%1,%2,%3}, [%4];"
                 : "=r"(r[0]), "=r"(r[1]), "=r"(r[2]), "=r"(r[3]) : "r"(addr));
}
__device__ __forceinline__ void mma_bf16(float* d, const uint32_t* a,
                                         uint32_t b0, uint32_t b1) {
    asm volatile(
        "mma.sync.aligned.m16n8k16.row.col.f32.bf16.bf16.f32 "
        "{%0,%1,%2,%3}, {%4,%5,%6,%7}, {%8,%9}, {%0,%1,%2,%3};"
        : "+f"(d[0]), "+f"(d[1]), "+f"(d[2]), "+f"(d[3])
        : "r"(a[0]), "r"(a[1]), "r"(a[2]), "r"(a[3]), "r"(b0), "r"(b1));
}
__device__ __forceinline__ uint32_t pack_bf2(__nv_bfloat16 a, __nv_bfloat16 b) {
    __nv_bfloat162 t;
    t.x = a; t.y = b;
    return *reinterpret_cast<uint32_t*>(&t);
}
__device__ __forceinline__ void cvt8(const float4 f0, const float4 f1, uint4& hu, uint4& lu) {
    float f[8] = {f0.x, f0.y, f0.z, f0.w, f1.x, f1.y, f1.z, f1.w};
    __nv_bfloat16 h[8], l[8];
    #pragma unroll
    for (int i = 0; i < 8; i++) {
        h[i] = __float2bfloat16_rn(f[i]);
        l[i] = __float2bfloat16_rn(f[i] - __bfloat162float(h[i]));
    }
    hu.x = pack_bf2(h[0], h[1]); hu.y = pack_bf2(h[2], h[3]);
    hu.z = pack_bf2(h[4], h[5]); hu.w = pack_bf2(h[6], h[7]);
    lu.x = pack_bf2(l[0], l[1]); lu.y = pack_bf2(l[2], l[3]);
    lu.z = pack_bf2(l[4], l[5]); lu.w = pack_bf2(l[6], l[7]);
}

// ---------------------------------------------------------------------------
// Prep: transpose + bf16-split W[D,P] -> Wt_{hi,lo}[proj][P][D]
// ---------------------------------------------------------------------------
__global__ void prep_kernel(const float* __restrict__ Wp, const float* __restrict__ Ws,
                            const float* __restrict__ Wq, const float* __restrict__ Wr)
{
    __shared__ float t[32][33];
    const float* W;
    switch (blockIdx.z) {
        case 0:  W = Wp; break;
        case 1:  W = Ws; break;
        case 2:  W = Wq; break;
        default: W = Wr; break;
    }
    const int p0 = blockIdx.x * 32, d0 = blockIdx.y * 32;
    const int tx = threadIdx.x, ty = threadIdx.y;
    #pragma unroll
    for (int k = 0; k < 4; k++)
        t[ty + k * 8][tx] = W[(size_t)(d0 + ty + k * 8) * PDIM + p0 + tx];
    __syncthreads();
    #pragma unroll
    for (int k = 0; k < 4; k++) {
        const int p = p0 + ty + k * 8;
        const float v = t[tx][ty + k * 8];
        __nv_bfloat16 h = __float2bfloat16_rn(v);
        __nv_bfloat16 l = __float2bfloat16_rn(v - __bfloat162float(h));
        const size_t o = ((size_t)blockIdx.z * PDIM + p) * DDIM + d0 + tx;
        g_wt_hi[o] = h;
        g_wt_lo[o] = l;
    }
}

// ---------------------------------------------------------------------------
// bf16x3 GEMM via mma.sync: CTA tile 256x128, BK=32, 16 warps (8M x 2N),
// warp tile 32x64. Pass-separated MMA ordering (hi.hi | hi.lo | lo.hi) so
// each accumulator's dependent MMAs are spaced 16 independent MMAs apart.
// Double-buffered smem; cp.async for pre-split W; X converted in registers.
// ---------------------------------------------------------------------------
#define BK      32
#define PAD     40            // smem row stride in bf16 (conflict-free ldmatrix)
#define OFF_AH  0             // 256*40*2 = 20480
#define OFF_AL  20480
#define OFF_BH  40960         // 128*40*2 = 10240
#define OFF_BL  51200
#define STAGE   61440
#define NCHUNK  (DDIM / BK)   // 64
#define GEMM_SMEM (2 * STAGE) // 122880

__global__ void __launch_bounds__(512, 1) gemm_kernel(
    const float* __restrict__ X,
    const float* __restrict__ bp, const float* __restrict__ bs,
    const float* __restrict__ bq,
    float* __restrict__ out)
{
    extern __shared__ char smem[];
    __shared__ float s_bias[128];
    const uint32_t sb = smem_u32(smem);

    const int tid  = threadIdx.x;
    const int proj = blockIdx.x >> 2;
    const int bcol = (blockIdx.x & 3) * 128;
    const int brow = blockIdx.y * 256;

    float* C;
    const float* bias;
    switch (proj) {
        case 0:  C = out;   bias = bp;      break;
        case 1:  C = g_sig; bias = bs;      break;
        case 2:  C = g_psi; bias = bq;      break;
        default: C = g_v;   bias = nullptr; break;
    }
    if (tid < 128) s_bias[tid] = bias ? bias[bcol + tid] : 0.0f;

    const int lane = tid & 31, wid = tid >> 5;
    const int warp_m = (wid & 7) * 32;
    const int warp_n = (wid >> 3) * 64;

    // A staging: 256 rows x 32 cols fp32; 2 threads/row, 16 cols each
    const int arow = tid >> 1;             // 0..255
    const int acb  = (tid & 1) * 16;       // col base 0/16
    const float* aptr = X + (size_t)(brow + arow) * DDIM + acb;

    // B staging: 128 rows x 32 bf16 cols (hi+lo); 4 threads/row, 8 cols each
    const int bro = tid >> 2;              // 0..127
    const int bcb = (tid & 3) * 8;
    const __nv_bfloat16* wtH = g_wt_hi + (size_t)(proj * PDIM + bcol + bro) * DDIM + bcb;
    const __nv_bfloat16* wtL = g_wt_lo + (size_t)(proj * PDIM + bcol + bro) * DDIM + bcb;

    // ldmatrix per-lane address pieces
    const int a_r  = warp_m + (lane & 15);
    const int a_cs = (lane >> 4) * 8;
    const int b_r  = warp_n + (lane >> 4) * 8 + (lane & 7);
    const int b_cs = ((lane >> 3) & 1) * 8;

    float acc[2][8][4];
    #pragma unroll
    for (int mt = 0; mt < 2; mt++)
        #pragma unroll
        for (int n = 0; n < 8; n++)
            #pragma unroll
            for (int q = 0; q < 4; q++) acc[mt][n][q] = 0.0f;

    float4 fA[4];
    #define LOAD_A_REGS(ch) do { \
        const float* p_ = aptr + (ch) * BK; \
        fA[0] = *(const float4*)(p_ + 0); \
        fA[1] = *(const float4*)(p_ + 4); \
        fA[2] = *(const float4*)(p_ + 8); \
        fA[3] = *(const float4*)(p_ + 12); \
    } while (0)

    #define STORE_A_SMEM(st_) do { \
        uint4 h0, l0, h1, l1; \
        cvt8(fA[0], fA[1], h0, l0); \
        cvt8(fA[2], fA[3], h1, l1); \
        const uint32_t o_ = (st_) + (uint32_t)(arow * PAD + acb) * 2; \
        *(uint4*)(smem + o_ + OFF_AH)      = h0; \
        *(uint4*)(smem + o_ + OFF_AH + 16) = h1; \
        *(uint4*)(smem + o_ + OFF_AL)      = l0; \
        *(uint4*)(smem + o_ + OFF_AL + 16) = l1; \
    } while (0)

    #define ISSUE_B_CP(ch, st_) do { \
        const uint32_t o_ = sb + (st_) + (uint32_t)(bro * PAD + bcb) * 2; \
        cp16(o_ + OFF_BH, wtH + (ch) * BK); \
        cp16(o_ + OFF_BL, wtL + (ch) * BK); \
        cp_commit(); \
    } while (0)

    // prologue
    ISSUE_B_CP(0, 0);
    LOAD_A_REGS(0);
    STORE_A_SMEM(0u);
    cp_wait0();
    __syncthreads();

    for (int ch = 0; ch < NCHUNK; ch++) {
        const uint32_t cur = (ch & 1) * STAGE;
        const uint32_t nxt = ((ch + 1) & 1) * STAGE;

        if (ch + 1 < NCHUNK) {
            ISSUE_B_CP(ch + 1, nxt);
            LOAD_A_REGS(ch + 1);
        }

        const uint32_t sAh = sb + cur + OFF_AH;
        const uint32_t sAl = sb + cur + OFF_AL;
        const uint32_t sBh = sb + cur + OFF_BH;
        const uint32_t sBl = sb + cur + OFF_BL;

        #pragma unroll
        for (int ks = 0; ks < 2; ks++) {
            uint32_t ah[2][4], al[2][4], bh[4][4], bl[4][4];
            #pragma unroll
            for (int mt = 0; mt < 2; mt++) {
                const uint32_t ao = (uint32_t)((a_r + mt * 16) * PAD + ks * 16 + a_cs) * 2;
                ldsm_x4(ah[mt], sAh + ao);
                ldsm_x4(al[mt], sAl + ao);
            }
            #pragma unroll
            for (int ng = 0; ng < 4; ng++) {
                const uint32_t bo = (uint32_t)((b_r + ng * 16) * PAD + ks * 16 + b_cs) * 2;
                ldsm_x4(bh[ng], sBh + bo);
                ldsm_x4(bl[ng], sBl + bo);
            }
            // pass 1: hi*hi (16 independent MMAs)
            #pragma unroll
            for (int mt = 0; mt < 2; mt++)
                #pragma unroll
                for (int ng = 0; ng < 4; ng++) {
                    mma_bf16(acc[mt][ng * 2],     ah[mt], bh[ng][0], bh[ng][1]);
                    mma_bf16(acc[mt][ng * 2 + 1], ah[mt], bh[ng][2], bh[ng][3]);
                }
            // pass 2: hi*lo
            #pragma unroll
            for (int mt = 0; mt < 2; mt++)
                #pragma unroll
                for (int ng = 0; ng < 4; ng++) {
                    mma_bf16(acc[mt][ng * 2],     ah[mt], bl[ng][0], bl[ng][1]);
                    mma_bf16(acc[mt][ng * 2 + 1], ah[mt], bl[ng][2], bl[ng][3]);
                }
            // pass 3: lo*hi
            #pragma unroll
            for (int mt = 0; mt < 2; mt++)
                #pragma unroll
                for (int ng = 0; ng < 4; ng++) {
                    mma_bf16(acc[mt][ng * 2],     al[mt], bh[ng][0], bh[ng][1]);
                    mma_bf16(acc[mt][ng * 2 + 1], al[mt], bh[ng][2], bh[ng][3]);
                }
        }

        if (ch + 1 < NCHUNK) {
            STORE_A_SMEM(nxt);
            cp_wait0();
            __syncthreads();
        }
    }

    // epilogue
    #pragma unroll
    for (int mt = 0; mt < 2; mt++) {
        const int r0 = brow + warp_m + mt * 16 + (lane >> 2);
        #pragma unroll
        for (int n8 = 0; n8 < 8; n8++) {
            const int c = warp_n + n8 * 8 + (lane & 3) * 2;
            float2 v0, v1;
            v0.x = acc[mt][n8][0] + s_bias[c];
            v0.y = acc[mt][n8][1] + s_bias[c + 1];
            v1.x = acc[mt][n8][2] + s_bias[c];
            v1.y = acc[mt][n8][3] + s_bias[c + 1];
            *(float2*)(C + (size_t)r0 * PDIM + bcol + c)       = v0;
            *(float2*)(C + (size_t)(r0 + 8) * PDIM + bcol + c) = v1;
        }
    }
}

// ---------------------------------------------------------------------------
// Per-(b,f) attention: scores = sig @ psi^T [36x36], softmax, r_hat = A @ v.
// ---------------------------------------------------------------------------
#define RS 516
#define SC 37
#define ATTN_SMEM_FLOATS (2 * NOBJ * RS + NOBJ * SC)

__global__ void __launch_bounds__(256) attn_kernel(float* __restrict__ out)
{
    extern __shared__ float sm[];
    float* s_psi = sm;
    float* s_buf = sm + NOBJ * RS;
    float* s_sc  = sm + 2 * NOBJ * RS;

    const int bf  = blockIdx.x;
    const int tid = threadIdx.x;

    const float* sigg = g_sig + (size_t)bf * NOBJ * PDIM;
    const float* psig = g_psi + (size_t)bf * NOBJ * PDIM;
    const float* vg   = g_v   + (size_t)bf * NOBJ * PDIM;

    for (int i = tid; i < NOBJ * 128; i += 256) {
        const int n = i >> 7, p4 = (i & 127) << 2;
        *(float4*)&s_buf[n * RS + p4] = *(const float4*)&sigg[n * PDIM + p4];
        *(float4*)&s_psi[n * RS + p4] = *(const float4*)&psig[n * PDIM + p4];
    }
    __syncthreads();

    {
        const int ti = tid & 15;
        const int tj = tid >> 4;
        const bool nok2 = (tj + 32) < NOBJ;
        const bool mok2 = (ti + 32) < NOBJ;
        const int tj2 = nok2 ? tj + 32 : 0;
        const int ti2 = mok2 ? ti + 32 : 0;

        float acc[3][3];
        #pragma unroll
        for (int a = 0; a < 3; a++)
            #pragma unroll
            for (int b = 0; b < 3; b++) acc[a][b] = 0.0f;

        for (int k = 0; k < PDIM; k += 4) {
            const float4 a0 = *(const float4*)&s_buf[(tj)      * RS + k];
            const float4 a1 = *(const float4*)&s_buf[(tj + 16) * RS + k];
            const float4 a2 = *(const float4*)&s_buf[(tj2)     * RS + k];
            const float4 b0 = *(const float4*)&s_psi[(ti)      * RS + k];
            const float4 b1 = *(const float4*)&s_psi[(ti + 16) * RS + k];
            const float4 b2 = *(const float4*)&s_psi[(ti2)     * RS + k];
            acc[0][0] += a0.x*b0.x + a0.y*b0.y + a0.z*b0.z + a0.w*b0.w;
            acc[0][1] += a0.x*b1.x + a0.y*b1.y + a0.z*b1.z + a0.w*b1.w;
            acc[0][2] += a0.x*b2.x + a0.y*b2.y + a0.z*b2.z + a0.w*b2.w;
            acc[1][0] += a1.x*b0.x + a1.y*b0.y + a1.z*b0.z + a1.w*b0.w;
            acc[1][1] += a1.x*b1.x + a1.y*b1.y + a1.z*b1.z + a1.w*b1.w;
            acc[1][2] += a1.x*b2.x + a1.y*b2.y + a1.z*b2.z + a1.w*b2.w;
            acc[2][0] += a2.x*b0.x + a2.y*b0.y + a2.z*b0.z + a2.w*b0.w;
            acc[2][1] += a2.x*b1.x + a2.y*b1.y + a2.z*b1.z + a2.w*b1.w;
            acc[2][2] += a2.x*b2.x + a2.y*b2.y + a2.z*b2.z + a2.w*b2.w;
        }
        #pragma unroll
        for (int a = 0; a < 3; a++) {
            const int n = tj + 16 * a;
            if (n >= NOBJ) break;
            #pragma unroll
            for (int b = 0; b < 3; b++) {
                const int m = ti + 16 * b;
                if (m < NOBJ) s_sc[n * SC + m] = acc[a][b];
            }
        }
    }
    __syncthreads();

    if (tid < NOBJ) {
        float mx = -1e30f;
        #pragma unroll
        for (int m = 0; m < NOBJ; m++) mx = fmaxf(mx, s_sc[tid * SC + m]);
        float s = 0.0f;
        #pragma unroll
        for (int m = 0; m < NOBJ; m++) {
            const float e = __expf(s_sc[tid * SC + m] - mx);
            s_sc[tid * SC + m] = e;
            s += e;
        }
        const float inv = 1.0f / s;
        #pragma unroll
        for (int m = 0; m < NOBJ; m++) s_sc[tid * SC + m] *= inv;
    }
    __syncthreads();

    for (int i = tid; i < NOBJ * 128; i += 256) {
        const int n = i >> 7, p4 = (i & 127) << 2;
        *(float4*)&s_buf[n * RS + p4] = *(const float4*)&vg[n * PDIM + p4];
    }
    __syncthreads();

    float* rhat = out + (size_t)MTOT * PDIM + (size_t)bf * NOBJ * PDIM;
    #pragma unroll
    for (int p0 = 0; p0 < PDIM; p0 += 256) {
        const int p = p0 + tid;
        float vr[NOBJ];
        #pragma unroll
        for (int m = 0; m < NOBJ; m++) vr[m] = s_buf[m * RS + p];
        #pragma unroll 4
        for (int n = 0; n < NOBJ; n++) {
            float s = 0.0f;
            #pragma unroll
            for (int m = 0; m < NOBJ; m++)
                s = fmaf(s_sc[n * SC + m], vr[m], s);
            rhat[n * PDIM + p] = s;
        }
    }
}

// ---------------------------------------------------------------------------
extern "C" void kernel_launch(void* const* d_in, const int* in_sizes, int n_in,
                              void* d_out, int out_size)
{
    const float* X   = (const float*)d_in[0];
    const float* Wp  = (const float*)d_in[1];
    const float* bp  = (const float*)d_in[2];
    const float* Ws  = (const float*)d_in[3];
    const float* bs  = (const float*)d_in[4];
    const float* Wq  = (const float*)d_in[5];
    const float* bq  = (const float*)d_in[6];
    const float* Wr  = (const float*)d_in[7];
    float* out = (float*)d_out;

    prep_kernel<<<dim3(PDIM / 32, DDIM / 32, 4), dim3(32, 8)>>>(Wp, Ws, Wq, Wr);

    cudaFuncSetAttribute(gemm_kernel,
                         cudaFuncAttributeMaxDynamicSharedMemorySize, GEMM_SMEM);
    gemm_kernel<<<dim3(16, MTOT / 256), 512, GEMM_SMEM>>>(X, bp, bs, bq, out);

    const int attn_smem = ATTN_SMEM_FLOATS * (int)sizeof(float);
    cudaFuncSetAttribute(attn_kernel,
                         cudaFuncAttributeMaxDynamicSharedMemorySize, attn_smem);
    attn_kernel<<<NBF, 256, attn_smem>>>(out);
}